// round 13
// baseline (speedup 1.0000x reference)
#include <cuda_runtime.h>
#include <cuda_fp16.h>
#include <cstdint>

typedef uint32_t u32;

// ---------------------------------------------------------------------------
// Triaffine, tensor-core fp16 mma (fp32 accum), 2 GEMM kernels:
//  K1: X{1,2} = l1(fp16) @ W{1,2}(fp16) + bias              -> g_X fp16
//  K23 (fused, per (m, 128-j tile)):
//    s1: A_r = l2 @ X2 + bias, *h2  -> smem pair (fp16 hi/lo)
//    s2: T   = pair @ W3T (2-term), *h1 -> smem fp32 (overwrites pair)
//    s3: A_l = l2 @ X1 + bias;  out[j] = sum_c A_l[j,c] * T[j,c]
// v5: 64x64 warp tiles (4x8 atoms, 8 warps/CTA of 256 thr) -- halves LDSM
// traffic per mma vs 32x64, moving the kernels from crossbar-parity to
// mma-bound. CTA tile 128x256 everywhere.
// ---------------------------------------------------------------------------

#define WSZ 16908544ull              // 257*65792
#define XSZ (2048ull*65792)

__device__ __half g_L1[2048ull*256], g_L2[2048ull*256];
__device__ __half g_W[2ull*WSZ];                   // W1 | W2 (fp16)
__device__ __half g_X[2ull*XSZ];                   // X1 | X2 (fp16)
__device__ __half g_W3T[256*256];                  // W3T[d][c] (fp16)

// staging buffer: [A 8192 | B 16384] x 3
#define BUF     24576
#define SMEM1   73728
// K23 extra regions
#define FSM_P   73728                // pair: hi 64KB | lo 64KB; T (133120B) overlaps
#define FSM_H   206848               // h1 1KB | h2 1KB
#define FSM_RED 208896               // 4 x 128 floats
#define FSMEM   210944

// ---------------- PTX helpers ----------------
__device__ __forceinline__ u32 smem_u32(const void* p) {
    u32 a;
    asm("{ .reg .u64 t; cvta.to.shared.u64 t, %1; cvt.u32.u64 %0, t; }" : "=r"(a) : "l"(p));
    return a;
}
__device__ __forceinline__ void cpa16(u32 s, const void* g) {
    asm volatile("cp.async.cg.shared.global [%0], [%1], 16;" :: "r"(s), "l"(g));
}
#define CPA_COMMIT() asm volatile("cp.async.commit_group;" ::: "memory")
#define CPA_WAIT(n)  asm volatile("cp.async.wait_group %0;" :: "n"(n) : "memory")

__device__ __forceinline__ void ldm_x4(u32 addr, u32 r[4]) {
    asm volatile("ldmatrix.sync.aligned.m8n8.x4.shared.b16 {%0,%1,%2,%3}, [%4];"
        : "=r"(r[0]), "=r"(r[1]), "=r"(r[2]), "=r"(r[3]) : "r"(addr));
}
__device__ __forceinline__ void ldm_x4_t(u32 addr, u32 r[4]) {
    asm volatile("ldmatrix.sync.aligned.m8n8.x4.trans.shared.b16 {%0,%1,%2,%3}, [%4];"
        : "=r"(r[0]), "=r"(r[1]), "=r"(r[2]), "=r"(r[3]) : "r"(addr));
}
__device__ __forceinline__ void mma_f16(float c[4], const u32 a[4], u32 b0, u32 b1) {
    asm volatile("mma.sync.aligned.m16n8k16.row.col.f32.f16.f16.f32 "
        "{%0,%1,%2,%3}, {%4,%5,%6,%7}, {%8,%9}, {%0,%1,%2,%3};"
        : "+f"(c[0]), "+f"(c[1]), "+f"(c[2]), "+f"(c[3])
        : "r"(a[0]), "r"(a[1]), "r"(a[2]), "r"(a[3]), "r"(b0), "r"(b1));
}

// XOR swizzles (c = 16B chunk index within row)
__device__ __forceinline__ u32 sw_a(u32 base, int row, int c) {       // 64B rows
    return base + row * 64 + ((c ^ ((row >> 1) & 3)) << 4);
}
__device__ __forceinline__ u32 sw_b512(u32 base, int row, int c) {    // 512B rows
    return base + row * 512 + ((c ^ (row & 7)) << 4);
}

#define ZERO_ACC(acc)                                                         \
    _Pragma("unroll") for (int mi = 0; mi < 4; ++mi)                          \
    _Pragma("unroll") for (int ni = 0; ni < 8; ++ni)                          \
    _Pragma("unroll") for (int q = 0; q < 4; ++q) acc[mi][ni][q] = 0.0f;

// ---------------------------------------------------------------------------
// Staging (BK=32, 256 threads): A 128x32 (8KB), B 32x256 (16KB).
// ---------------------------------------------------------------------------
__device__ __forceinline__ void stage_f(u32 base, int tid,
    const __half* __restrict__ a,
    const __half* __restrict__ b, size_t bpitch, int k0)
{
    const int arow = tid >> 1, ac = (tid & 1) * 2;
    const __half* ga = a + (size_t)arow * 256 + k0 + ac * 8;
    cpa16(sw_a(base, arow, ac), ga);
    cpa16(sw_a(base, arow, ac + 1), ga + 8);
    const int brow = tid >> 3, bc = (tid & 7) * 4;
    const __half* gb = b + (size_t)(k0 + brow) * bpitch + bc * 8;
    cpa16(sw_b512(base + 8192, brow, bc),     gb);
    cpa16(sw_b512(base + 8192, brow, bc + 1), gb + 8);
    cpa16(sw_b512(base + 8192, brow, bc + 2), gb + 16);
    cpa16(sw_b512(base + 8192, brow, bc + 3), gb + 24);
}
__device__ __forceinline__ void stage_fB(u32 base, int tid,
    const __half* __restrict__ b, int k0)
{
    const int brow = tid >> 3, bc = (tid & 7) * 4;
    const __half* gb = b + (size_t)(k0 + brow) * 256 + bc * 8;
    cpa16(sw_b512(base, brow, bc),     gb);
    cpa16(sw_b512(base, brow, bc + 1), gb + 8);
    cpa16(sw_b512(base, brow, bc + 2), gb + 16);
    cpa16(sw_b512(base, brow, bc + 3), gb + 24);
}

// ---------------------------------------------------------------------------
// Warp tile 64x64 over one BK=32 chunk. 1-term: 8 LDSM, 64 mma.
// ---------------------------------------------------------------------------
__device__ __forceinline__ void compute64(float acc[4][8][4],
        u32 base, int warpM, int warpN, int lane)
{
    const int lr = lane & 15, lh = lane >> 4;
#pragma unroll
    for (int kk = 0; kk < 2; ++kk) {
        u32 af[4][4];
#pragma unroll
        for (int mi = 0; mi < 4; ++mi)
            ldm_x4(sw_a(base, warpM * 64 + mi * 16 + lr, kk * 2 + lh), af[mi]);
#pragma unroll
        for (int np = 0; np < 4; ++np) {
            u32 bf[4];
            ldm_x4_t(sw_b512(base + 8192, kk * 16 + lr, warpN * 8 + np * 2 + lh), bf);
#pragma unroll
            for (int mi = 0; mi < 4; ++mi) {
                mma_f16(acc[mi][np*2],   af[mi], bf[0], bf[1]);
                mma_f16(acc[mi][np*2+1], af[mi], bf[2], bf[3]);
            }
        }
    }
}
// pair-A (P resident): 12 LDSM, 128 mma. sChunk = s*4 global k-chunk base.
__device__ __forceinline__ void compute64p(float acc[4][8][4],
        u32 pHi, u32 pLo, u32 bBase, int sChunk, int warpM, int warpN, int lane)
{
    const int lr = lane & 15, lh = lane >> 4;
#pragma unroll
    for (int kk = 0; kk < 2; ++kk) {
        u32 afh[4][4], afl[4][4];
#pragma unroll
        for (int mi = 0; mi < 4; ++mi) {
            int row = warpM * 64 + mi * 16 + lr;
            int c = sChunk + kk * 2 + lh;
            u32 off = row * 512 + (((c ^ (row & 7))) << 4);
            ldm_x4(pHi + off, afh[mi]);
            ldm_x4(pLo + off, afl[mi]);
        }
#pragma unroll
        for (int np = 0; np < 4; ++np) {
            u32 bf[4];
            ldm_x4_t(sw_b512(bBase, kk * 16 + lr, warpN * 8 + np * 2 + lh), bf);
#pragma unroll
            for (int mi = 0; mi < 4; ++mi) {
                mma_f16(acc[mi][np*2],   afh[mi], bf[0], bf[1]);
                mma_f16(acc[mi][np*2],   afl[mi], bf[0], bf[1]);
                mma_f16(acc[mi][np*2+1], afh[mi], bf[2], bf[3]);
                mma_f16(acc[mi][np*2+1], afl[mi], bf[2], bf[3]);
            }
        }
    }
}

// 3-buffer pipeline, prefetch depth 2, one barrier per BK=32 stage
#define FLOOP(STG, CMP)                                                       \
    STG(0, 0); CPA_COMMIT();                                                  \
    STG(1, 1); CPA_COMMIT();                                                  \
    for (int s = 0; s < 8; ++s) {                                             \
        if (s == 7) { CPA_WAIT(0); } else { CPA_WAIT(1); }                    \
        __syncthreads();                                                      \
        if (s < 6) { STG((s + 2) % 3, s + 2); CPA_COMMIT(); }                 \
        CMP;                                                                  \
    }

// ---------------------------------------------------------------------------
// Prep: fp32 -> fp16 (dest: 0 L1, 1 L2, 2 W1, 3 W2)
// ---------------------------------------------------------------------------
__global__ void k_prep(const float* __restrict__ src, int dest, size_t cnt)
{
    size_t i = ((size_t)blockIdx.x * 256 + threadIdx.x) * 8;
    if (i >= cnt) return;
    __half* d;
    switch (dest) {
        case 0:  d = g_L1; break;
        case 1:  d = g_L2; break;
        case 2:  d = g_W;  break;
        default: d = g_W + WSZ; break;
    }
    float4 v0 = *reinterpret_cast<const float4*>(src + i);
    float4 v1 = *reinterpret_cast<const float4*>(src + i + 4);
    float x[8] = {v0.x, v0.y, v0.z, v0.w, v1.x, v1.y, v1.z, v1.w};
    u32 o[4];
#pragma unroll
    for (int j = 0; j < 4; ++j) {
        __half2 h = __floats2half2_rn(x[2*j], x[2*j+1]);
        o[j] = *reinterpret_cast<u32*>(&h);
    }
    *reinterpret_cast<uint4*>(d + i) = make_uint4(o[0], o[1], o[2], o[3]);
}

__global__ void k_prep_w3(const float* __restrict__ W3)
{
    __shared__ float t[32][33];
    int bx = blockIdx.x * 32, by = blockIdx.y * 32;
    t[threadIdx.y][threadIdx.x] = W3[(size_t)(by + threadIdx.y) * 256 + bx + threadIdx.x];
    __syncthreads();
    g_W3T[(size_t)(bx + threadIdx.y) * 256 + by + threadIdx.x] =
        __float2half_rn(t[threadIdx.x][threadIdx.y]);
}

// ---------------------------------------------------------------------------
// K1: grid (16 mt, 257 nt, 2 w). D[128 m][256 bc], K=256 over a -> X fp16.
// 256 threads, 8 warps (2 warpM x 4 warpN), warp tile 64x64.
// ---------------------------------------------------------------------------
__global__ void __launch_bounds__(256, 1)
k1_gemm()
{
    extern __shared__ char smem[];
    const int tid = threadIdx.x, lane = tid & 31, wid = tid >> 5;
    const int warpM = wid & 1, warpN = wid >> 1;
    const int mBase = blockIdx.x * 128;
    const size_t n0 = (size_t)blockIdx.y * 256;
    const int w = blockIdx.z;
    const __half* WP = g_W + (size_t)w * WSZ + n0;
    __half* XP       = g_X + (size_t)w * XSZ;
    const __half* AP = g_L1 + (size_t)mBase * 256;
    const u32 sb = smem_u32(smem);

    float acc[4][8][4];
    ZERO_ACC(acc)

#define K1_STG(buf, s) stage_f(sb + (buf) * BUF, tid, AP, WP, 65792, (s) * 32)
    FLOOP(K1_STG, compute64(acc, sb + (s % 3) * BUF, warpM, warpN, lane))
#undef K1_STG

    const int gq = lane >> 2, t = lane & 3;
#pragma unroll
    for (int mi = 0; mi < 4; ++mi) {
        int row = mBase + warpM * 64 + mi * 16 + gq;
#pragma unroll
        for (int ni = 0; ni < 8; ++ni) {
            int colL = warpN * 64 + ni * 8 + t * 2;
            __half2 b2 = *reinterpret_cast<const __half2*>(WP + 256ull * 65792 + colL);
            float b0 = __half2float(__low2half(b2));
            float b1 = __half2float(__high2half(b2));
            size_t col = n0 + colL;
            __half2 o0 = __floats2half2_rn(acc[mi][ni][0] + b0, acc[mi][ni][1] + b1);
            __half2 o1 = __floats2half2_rn(acc[mi][ni][2] + b0, acc[mi][ni][3] + b1);
            *reinterpret_cast<__half2*>(XP + (size_t)row * 65792 + col) = o0;
            *reinterpret_cast<__half2*>(XP + (size_t)(row + 8) * 65792 + col) = o1;
        }
    }
}

// ---------------------------------------------------------------------------
// K23 fused: grid (2 jt, 2048 m), 256 threads, CTA tile 128 j x 256 (c|d).
// ---------------------------------------------------------------------------
__global__ void __launch_bounds__(256, 1)
k23_fused(const float* __restrict__ h1, const float* __restrict__ h2,
          float* __restrict__ out)
{
    extern __shared__ char smem[];
    const int tid = threadIdx.x, lane = tid & 31, wid = tid >> 5;
    const int warpM = wid & 1, warpN = wid >> 1;
    const int jt = blockIdx.x, m = blockIdx.y;
    const u32 sb = smem_u32(smem);
    const u32 pHi = sb + FSM_P, pLo = sb + FSM_P + 65536;
    float* Tp  = reinterpret_cast<float*>(smem + FSM_P);     // pitch 260 floats
    float* h1s = reinterpret_cast<float*>(smem + FSM_H);
    float* h2s = reinterpret_cast<float*>(smem + FSM_H + 1024);
    float* red = reinterpret_cast<float*>(smem + FSM_RED);

    const __half* AP  = g_L2 + ((size_t)(m >> 8) * 256 + (size_t)jt * 128) * 256;
    const __half* X1P = g_X + (size_t)m * 65792;
    const __half* X2P = g_X + XSZ + (size_t)m * 65792;

    h1s[tid] = h1[(size_t)m * 256 + tid];
    h2s[tid] = h2[(size_t)m * 256 + tid];

    const int gq = lane >> 2, t = lane & 3;
    float acc[4][8][4];

    // ---------------- stage 1: A_r = l2 @ X2 + bias, *h2 -> P pair ----------
    ZERO_ACC(acc)
#define S1(buf, s) stage_f(sb + (buf) * BUF, tid, AP, X2P, 256, (s) * 32)
    FLOOP(S1, compute64(acc, sb + (s % 3) * BUF, warpM, warpN, lane))
#undef S1

#pragma unroll
    for (int mi = 0; mi < 4; ++mi) {
        int j0 = warpM * 64 + mi * 16 + gq;
#pragma unroll
        for (int ni = 0; ni < 8; ++ni) {
            int c = warpN * 64 + ni * 8 + t * 2;
            __half2 b2 = *reinterpret_cast<const __half2*>(X2P + 65536 + c);
            float b0 = __half2float(__low2half(b2));
            float b1 = __half2float(__high2half(b2));
            float v00 = (acc[mi][ni][0] + b0) * h2s[c];
            float v01 = (acc[mi][ni][1] + b1) * h2s[c + 1];
            float v10 = (acc[mi][ni][2] + b0) * h2s[c];
            float v11 = (acc[mi][ni][3] + b1) * h2s[c + 1];
            u32 chunk = (u32)(warpN * 8 + ni);
            u32 o0 = j0 * 512 + ((chunk ^ (j0 & 7)) << 4) + t * 4;
            int j1 = j0 + 8;
            u32 o1 = j1 * 512 + ((chunk ^ (j1 & 7)) << 4) + t * 4;
            __half h0 = __float2half_rn(v00), hh1 = __float2half_rn(v01);
            __half l0 = __float2half_rn(v00 - __half2float(h0));
            __half l1 = __float2half_rn(v01 - __half2float(hh1));
            *reinterpret_cast<__half2*>(smem + (pHi - sb) + o0) = __halves2half2(h0, hh1);
            *reinterpret_cast<__half2*>(smem + (pLo - sb) + o0) = __halves2half2(l0, l1);
            h0 = __float2half_rn(v10); hh1 = __float2half_rn(v11);
            l0 = __float2half_rn(v10 - __half2float(h0));
            l1 = __float2half_rn(v11 - __half2float(hh1));
            *reinterpret_cast<__half2*>(smem + (pHi - sb) + o1) = __halves2half2(h0, hh1);
            *reinterpret_cast<__half2*>(smem + (pLo - sb) + o1) = __halves2half2(l0, l1);
        }
    }
    __syncthreads();   // P complete before stage-2 staging/compute

    // ---------------- stage 2: T = P(pair) @ W3T, *h1 -> T (overwrites P) ---
    ZERO_ACC(acc)
#define S2(buf, s) stage_fB(sb + (buf) * BUF, tid, g_W3T, (s) * 32)
    FLOOP(S2, compute64p(acc, pHi, pLo, sb + (s % 3) * BUF, s * 4, warpM, warpN, lane))
#undef S2

    __syncthreads();   // all P reads done; safe to overwrite with T
#pragma unroll
    for (int mi = 0; mi < 4; ++mi) {
        int j0 = warpM * 64 + mi * 16 + gq;
#pragma unroll
        for (int ni = 0; ni < 8; ++ni) {
            int c = warpN * 64 + ni * 8 + t * 2;
            float s0 = h1s[c], s1 = h1s[c + 1];
            *reinterpret_cast<float2*>(Tp + (size_t)j0 * 260 + c) =
                make_float2(acc[mi][ni][0] * s0, acc[mi][ni][1] * s1);
            *reinterpret_cast<float2*>(Tp + (size_t)(j0 + 8) * 260 + c) =
                make_float2(acc[mi][ni][2] * s0, acc[mi][ni][3] * s1);
        }
    }
    __syncthreads();   // T visible; staging bufs free for stage 3

    // ---------------- stage 3: A_l = l2 @ X1 + bias; dot with T -------------
    ZERO_ACC(acc)
#define S3(buf, s) stage_f(sb + (buf) * BUF, tid, AP, X1P, 256, (s) * 32)
    FLOOP(S3, compute64(acc, sb + (s % 3) * BUF, warpM, warpN, lane))
#undef S3

    float rs[4][2];
#pragma unroll
    for (int mi = 0; mi < 4; ++mi) { rs[mi][0] = 0.0f; rs[mi][1] = 0.0f; }
#pragma unroll
    for (int mi = 0; mi < 4; ++mi) {
        int j0 = warpM * 64 + mi * 16 + gq;
#pragma unroll
        for (int ni = 0; ni < 8; ++ni) {
            int c = warpN * 64 + ni * 8 + t * 2;
            __half2 b2 = *reinterpret_cast<const __half2*>(X1P + 65536 + c);
            float b0 = __half2float(__low2half(b2));
            float b1 = __half2float(__high2half(b2));
            float2 t0 = *reinterpret_cast<const float2*>(Tp + (size_t)j0 * 260 + c);
            float2 t1 = *reinterpret_cast<const float2*>(Tp + (size_t)(j0 + 8) * 260 + c);
            rs[mi][0] += (acc[mi][ni][0] + b0) * t0.x + (acc[mi][ni][1] + b1) * t0.y;
            rs[mi][1] += (acc[mi][ni][2] + b0) * t1.x + (acc[mi][ni][3] + b1) * t1.y;
        }
    }

    // reduce over the 4 lanes (t) sharing each row, then across warpN
#pragma unroll
    for (int mi = 0; mi < 4; ++mi)
#pragma unroll
        for (int h = 0; h < 2; ++h) {
            rs[mi][h] += __shfl_xor_sync(0xffffffffu, rs[mi][h], 1);
            rs[mi][h] += __shfl_xor_sync(0xffffffffu, rs[mi][h], 2);
        }
    if (t == 0) {
#pragma unroll
        for (int mi = 0; mi < 4; ++mi) {
            int j0 = warpM * 64 + mi * 16 + gq;
            red[warpN * 128 + j0]     = rs[mi][0];
            red[warpN * 128 + j0 + 8] = rs[mi][1];
        }
    }
    __syncthreads();
    if (tid < 128)
        out[(size_t)m * 256 + jt * 128 + tid] =
            red[tid] + red[128 + tid] + red[256 + tid] + red[384 + tid];
}

// ---------------------------------------------------------------------------
extern "C" void kernel_launch(void* const* d_in, const int* in_sizes, int n_in,
                              void* d_out, int out_size)
{
    const float* layer1 = (const float*)d_in[0];
    const float* layer2 = (const float*)d_in[1];
    const float* h1     = (const float*)d_in[2];
    const float* h2     = (const float*)d_in[3];
    const float* W1     = (const float*)d_in[4];
    const float* W2     = (const float*)d_in[5];
    const float* W3     = (const float*)d_in[6];
    float* out = (float*)d_out;

    cudaFuncSetAttribute(k1_gemm,   cudaFuncAttributeMaxDynamicSharedMemorySize, SMEM1);
    cudaFuncSetAttribute(k23_fused, cudaFuncAttributeMaxDynamicSharedMemorySize, FSMEM);

    k_prep<<<256,  256>>>(layer1, 0, 524288ull);
    k_prep<<<256,  256>>>(layer2, 1, 524288ull);
    k_prep<<<8257, 256>>>(W1, 2, WSZ);
    k_prep<<<8257, 256>>>(W2, 3, WSZ);
    k_prep_w3<<<dim3(8, 8), dim3(32, 32)>>>(W3);

    k1_gemm<<<dim3(16, 257, 2), 256, SMEM1>>>();
    k23_fused<<<dim3(2, 2048), 256, FSMEM>>>(h1, h2, out);
}

// round 14
// speedup vs baseline: 1.3517x; 1.3517x over previous
#include <cuda_runtime.h>
#include <cuda_fp16.h>
#include <cstdint>

typedef uint32_t u32;

// ---------------------------------------------------------------------------
// Triaffine, tensor-core fp16 mma (fp32 accum), 2 GEMM kernels:
//  K1: X{1,2} = l1(fp16) @ W{1,2}(fp16) + bias              -> g_X fp16
//  K23 (fused, per (m, 128-j tile)):
//    s1: A_r = l2 @ X2 + bias, *h2  -> smem P (single fp16)
//    s2: T   = P @ W3T (1-term), *h1 -> smem fp32 (overwrites P)
//    s3: A_l = l2 @ X1 + bias;  out[j] = sum_c A_l[j,c] * T[j,c]
// v6 = R12 architecture (512-thr K23, 32x64 warp tiles, 16 warps) + stage-2
// single-term P (calibrated error model: +1 fp16 term in quadrature).
// ---------------------------------------------------------------------------

#define WSZ 16908544ull              // 257*65792
#define XSZ (2048ull*65792)

__device__ __half g_L1[2048ull*256], g_L2[2048ull*256];
__device__ __half g_W[2ull*WSZ];                   // W1 | W2 (fp16)
__device__ __half g_X[2ull*XSZ];                   // X1 | X2 (fp16)
__device__ __half g_W3T[256*256];                  // W3T[d][c] (fp16)

// ---- K1 smem (256 threads, 2 CTA/SM): [A 8192 | B 8192] x 4 ----
#define BUF12   16384
#define SMEM12  65536

// ---- K23 smem (512 threads, 1 CTA/SM) ----
#define FBUF    24576                // [A 8192 | B 16384] x 3
#define FSM_P   73728                // P hi 64KB; T fp32 (133120B) overlaps
#define FSM_H   206848               // h1 1KB | h2 1KB
#define FSM_RED 208896               // 4 x 128 floats
#define FSMEM   210944

// ---------------- PTX helpers ----------------
__device__ __forceinline__ u32 smem_u32(const void* p) {
    u32 a;
    asm("{ .reg .u64 t; cvta.to.shared.u64 t, %1; cvt.u32.u64 %0, t; }" : "=r"(a) : "l"(p));
    return a;
}
__device__ __forceinline__ void cpa16(u32 s, const void* g) {
    asm volatile("cp.async.cg.shared.global [%0], [%1], 16;" :: "r"(s), "l"(g));
}
#define CPA_COMMIT() asm volatile("cp.async.commit_group;" ::: "memory")
#define CPA_WAIT(n)  asm volatile("cp.async.wait_group %0;" :: "n"(n) : "memory")

__device__ __forceinline__ void ldm_x4(u32 addr, u32 r[4]) {
    asm volatile("ldmatrix.sync.aligned.m8n8.x4.shared.b16 {%0,%1,%2,%3}, [%4];"
        : "=r"(r[0]), "=r"(r[1]), "=r"(r[2]), "=r"(r[3]) : "r"(addr));
}
__device__ __forceinline__ void ldm_x4_t(u32 addr, u32 r[4]) {
    asm volatile("ldmatrix.sync.aligned.m8n8.x4.trans.shared.b16 {%0,%1,%2,%3}, [%4];"
        : "=r"(r[0]), "=r"(r[1]), "=r"(r[2]), "=r"(r[3]) : "r"(addr));
}
__device__ __forceinline__ void mma_f16(float c[4], const u32 a[4], u32 b0, u32 b1) {
    asm volatile("mma.sync.aligned.m16n8k16.row.col.f32.f16.f16.f32 "
        "{%0,%1,%2,%3}, {%4,%5,%6,%7}, {%8,%9}, {%0,%1,%2,%3};"
        : "+f"(c[0]), "+f"(c[1]), "+f"(c[2]), "+f"(c[3])
        : "r"(a[0]), "r"(a[1]), "r"(a[2]), "r"(a[3]), "r"(b0), "r"(b1));
}

// XOR swizzles (c = 16B chunk index within row)
__device__ __forceinline__ u32 sw_a(u32 base, int row, int c) {       // 64B rows
    return base + row * 64 + ((c ^ ((row >> 1) & 3)) << 4);
}
__device__ __forceinline__ u32 sw_b(u32 base, int row, int c) {       // 256B rows
    return base + row * 256 + ((c ^ (row & 7)) << 4);
}
__device__ __forceinline__ u32 sw_b512(u32 base, int row, int c) {    // 512B rows
    return base + row * 512 + ((c ^ (row & 7)) << 4);
}

#define ZERO_ACC(acc)                                                         \
    _Pragma("unroll") for (int mi = 0; mi < 2; ++mi)                          \
    _Pragma("unroll") for (int ni = 0; ni < 8; ++ni)                          \
    _Pragma("unroll") for (int q = 0; q < 4; ++q) acc[mi][ni][q] = 0.0f;

// ---------------------------------------------------------------------------
// K1 building blocks (256 threads, B rows 256B, CTA 128x128)
// ---------------------------------------------------------------------------
__device__ __forceinline__ void stage_s(u32 base, int tid,
    const __half* __restrict__ a, size_t apitch,
    const __half* __restrict__ b, size_t bpitch, int k0)
{
    const int arow = tid >> 1, ac = tid & 1;
    const __half* g = a + (size_t)arow * apitch + k0 + ac * 16;
    cpa16(sw_a(base, arow, ac * 2), g);
    cpa16(sw_a(base, arow, ac * 2 + 1), g + 8);
    const int brow = tid >> 3, bc = tid & 7;
    g = b + (size_t)(k0 + brow) * bpitch + bc * 16;
    cpa16(sw_b(base + 8192, brow, bc * 2), g);
    cpa16(sw_b(base + 8192, brow, bc * 2 + 1), g + 8);
}
__device__ __forceinline__ void compute_s(float acc[2][8][4],
        u32 base, int warpM, int warpN, int lane)
{
    const int lr = lane & 15, lh = lane >> 4;
#pragma unroll
    for (int kk = 0; kk < 2; ++kk) {
        u32 af[2][4];
#pragma unroll
        for (int mi = 0; mi < 2; ++mi)
            ldm_x4(sw_a(base, warpM * 32 + mi * 16 + lr, kk * 2 + lh), af[mi]);
#pragma unroll
        for (int np = 0; np < 4; ++np) {
            u32 bf[4];
            ldm_x4_t(sw_b(base + 8192, kk * 16 + lr, warpN * 8 + np * 2 + lh), bf);
#pragma unroll
            for (int mi = 0; mi < 2; ++mi) {
                mma_f16(acc[mi][np*2],   af[mi], bf[0], bf[1]);
                mma_f16(acc[mi][np*2+1], af[mi], bf[2], bf[3]);
            }
        }
    }
}

// ---------------------------------------------------------------------------
// K23 building blocks (512 threads, B rows 512B, CTA 128x256)
// ---------------------------------------------------------------------------
__device__ __forceinline__ void stage_f(u32 base, int tid,
    const __half* __restrict__ a, const __half* __restrict__ b, int k0)
{
    const int arow = tid >> 2, ac = tid & 3;
    cpa16(sw_a(base, arow, ac), a + (size_t)arow * 256 + k0 + ac * 8);
    const int brow = tid >> 4, bc = (tid & 15) * 2;
    const __half* g = b + (size_t)(k0 + brow) * 256 + bc * 8;
    cpa16(sw_b512(base + 8192, brow, bc), g);
    cpa16(sw_b512(base + 8192, brow, bc + 1), g + 8);
}
__device__ __forceinline__ void stage_fB(u32 base, int tid,
    const __half* __restrict__ b, int k0)
{
    const int brow = tid >> 4, bc = (tid & 15) * 2;
    const __half* g = b + (size_t)(k0 + brow) * 256 + bc * 8;
    cpa16(sw_b512(base, brow, bc), g);
    cpa16(sw_b512(base, brow, bc + 1), g + 8);
}
// single-A (l2 staged) GEMM chunk
__device__ __forceinline__ void compute_f(float acc[2][8][4],
        u32 base, int warpM, int warpN, int lane)
{
    const int lr = lane & 15, lh = lane >> 4;
#pragma unroll
    for (int kk = 0; kk < 2; ++kk) {
        u32 af[2][4];
#pragma unroll
        for (int mi = 0; mi < 2; ++mi)
            ldm_x4(sw_a(base, warpM * 32 + mi * 16 + lr, kk * 2 + lh), af[mi]);
#pragma unroll
        for (int np = 0; np < 4; ++np) {
            u32 bf[4];
            ldm_x4_t(sw_b512(base + 8192, kk * 16 + lr, warpN * 8 + np * 2 + lh), bf);
#pragma unroll
            for (int mi = 0; mi < 2; ++mi) {
                mma_f16(acc[mi][np*2],   af[mi], bf[0], bf[1]);
                mma_f16(acc[mi][np*2+1], af[mi], bf[2], bf[3]);
            }
        }
    }
}
// single-A with A resident in P (smem); sChunk = s*4 global k-chunk base
__device__ __forceinline__ void compute_fp1(float acc[2][8][4],
        u32 pHi, u32 bBase, int sChunk, int warpM, int warpN, int lane)
{
    const int lr = lane & 15, lh = lane >> 4;
#pragma unroll
    for (int kk = 0; kk < 2; ++kk) {
        u32 af[2][4];
#pragma unroll
        for (int mi = 0; mi < 2; ++mi) {
            int row = warpM * 32 + mi * 16 + lr;
            int c = sChunk + kk * 2 + lh;
            u32 off = row * 512 + (((c ^ (row & 7))) << 4);
            ldm_x4(pHi + off, af[mi]);
        }
#pragma unroll
        for (int np = 0; np < 4; ++np) {
            u32 bf[4];
            ldm_x4_t(sw_b512(bBase, kk * 16 + lr, warpN * 8 + np * 2 + lh), bf);
#pragma unroll
            for (int mi = 0; mi < 2; ++mi) {
                mma_f16(acc[mi][np*2],   af[mi], bf[0], bf[1]);
                mma_f16(acc[mi][np*2+1], af[mi], bf[2], bf[3]);
            }
        }
    }
}

// 3-buffer pipeline, prefetch depth 2, one barrier per BK=32 stage
#define FLOOP(STG, CMP)                                                       \
    STG(0, 0); CPA_COMMIT();                                                  \
    STG(1, 1); CPA_COMMIT();                                                  \
    for (int s = 0; s < 8; ++s) {                                             \
        if (s == 7) { CPA_WAIT(0); } else { CPA_WAIT(1); }                    \
        __syncthreads();                                                      \
        if (s < 6) { STG((s + 2) % 3, s + 2); CPA_COMMIT(); }                 \
        CMP;                                                                  \
    }

// K1 pipeline: 4 buffers, depth 3
#define MAINLOOP12(STG)                                                       \
    STG(0, 0); CPA_COMMIT();                                                  \
    STG(1, 1); CPA_COMMIT();                                                  \
    STG(2, 2); CPA_COMMIT();                                                  \
    for (int s = 0; s < 8; ++s) {                                             \
        if (s <= 5) { CPA_WAIT(2); } else if (s == 6) { CPA_WAIT(1); }        \
        else { CPA_WAIT(0); }                                                 \
        __syncthreads();                                                      \
        if (s < 5) { STG((s + 3) & 3, s + 3); CPA_COMMIT(); }                 \
        compute_s(acc, sb + (s & 3) * BUF12, warpM, warpN, lane);             \
    }

// ---------------------------------------------------------------------------
// Prep: fp32 -> fp16 (dest: 0 L1, 1 L2, 2 W1, 3 W2)
// ---------------------------------------------------------------------------
__global__ void k_prep(const float* __restrict__ src, int dest, size_t cnt)
{
    size_t i = ((size_t)blockIdx.x * 256 + threadIdx.x) * 8;
    if (i >= cnt) return;
    __half* d;
    switch (dest) {
        case 0:  d = g_L1; break;
        case 1:  d = g_L2; break;
        case 2:  d = g_W;  break;
        default: d = g_W + WSZ; break;
    }
    float4 v0 = *reinterpret_cast<const float4*>(src + i);
    float4 v1 = *reinterpret_cast<const float4*>(src + i + 4);
    float x[8] = {v0.x, v0.y, v0.z, v0.w, v1.x, v1.y, v1.z, v1.w};
    u32 o[4];
#pragma unroll
    for (int j = 0; j < 4; ++j) {
        __half2 h = __floats2half2_rn(x[2*j], x[2*j+1]);
        o[j] = *reinterpret_cast<u32*>(&h);
    }
    *reinterpret_cast<uint4*>(d + i) = make_uint4(o[0], o[1], o[2], o[3]);
}

__global__ void k_prep_w3(const float* __restrict__ W3)
{
    __shared__ float t[32][33];
    int bx = blockIdx.x * 32, by = blockIdx.y * 32;
    t[threadIdx.y][threadIdx.x] = W3[(size_t)(by + threadIdx.y) * 256 + bx + threadIdx.x];
    __syncthreads();
    g_W3T[(size_t)(bx + threadIdx.y) * 256 + by + threadIdx.x] =
        __float2half_rn(t[threadIdx.x][threadIdx.y]);
}

// ---------------------------------------------------------------------------
// K1: grid (16 mt, 514 nt, 2 w). D[128 m][128 bc], K=256 over a -> X fp16.
// ---------------------------------------------------------------------------
__global__ void __launch_bounds__(256, 2)
k1_gemm()
{
    extern __shared__ char smem[];
    const int tid = threadIdx.x, lane = tid & 31, wid = tid >> 5;
    const int warpM = wid & 3, warpN = wid >> 2;
    const int mBase = blockIdx.x * 128;
    const size_t n0 = (size_t)blockIdx.y * 128;
    const int w = blockIdx.z;
    const __half* WP = g_W + (size_t)w * WSZ + n0;
    __half* XP       = g_X + (size_t)w * XSZ;
    const __half* AP = g_L1 + (size_t)mBase * 256;
    const u32 sb = smem_u32(smem);

    float acc[2][8][4];
    ZERO_ACC(acc)

#define K1_STAGE(buf, s) stage_s(sb + (buf) * BUF12, tid, AP, 256, WP, 65792, (s) * 32)
    MAINLOOP12(K1_STAGE)
#undef K1_STAGE

    const int gq = lane >> 2, t = lane & 3;
#pragma unroll
    for (int mi = 0; mi < 2; ++mi) {
        int row = mBase + warpM * 32 + mi * 16 + gq;
#pragma unroll
        for (int ni = 0; ni < 8; ++ni) {
            int colL = warpN * 64 + ni * 8 + t * 2;
            __half2 b2 = *reinterpret_cast<const __half2*>(WP + 256ull * 65792 + colL);
            float b0 = __half2float(__low2half(b2));
            float b1 = __half2float(__high2half(b2));
            size_t col = n0 + colL;
            __half2 o0 = __floats2half2_rn(acc[mi][ni][0] + b0, acc[mi][ni][1] + b1);
            __half2 o1 = __floats2half2_rn(acc[mi][ni][2] + b0, acc[mi][ni][3] + b1);
            *reinterpret_cast<__half2*>(XP + (size_t)row * 65792 + col) = o0;
            *reinterpret_cast<__half2*>(XP + (size_t)(row + 8) * 65792 + col) = o1;
        }
    }
}

// ---------------------------------------------------------------------------
// K23 fused: grid (2 jt, 2048 m), 512 threads, CTA tile 128 j x 256 (c|d).
// ---------------------------------------------------------------------------
__global__ void __launch_bounds__(512, 1)
k23_fused(const float* __restrict__ h1, const float* __restrict__ h2,
          float* __restrict__ out)
{
    extern __shared__ char smem[];
    const int tid = threadIdx.x, lane = tid & 31, wid = tid >> 5;
    const int warpM = wid & 3, warpN = wid >> 2;     // 4 x 4 warps
    const int jt = blockIdx.x, m = blockIdx.y;
    const u32 sb = smem_u32(smem);
    const u32 pHi = sb + FSM_P;
    float* Tp  = reinterpret_cast<float*>(smem + FSM_P);     // pitch 260 floats
    float* h1s = reinterpret_cast<float*>(smem + FSM_H);
    float* h2s = reinterpret_cast<float*>(smem + FSM_H + 1024);
    float* red = reinterpret_cast<float*>(smem + FSM_RED);

    const __half* AP  = g_L2 + ((size_t)(m >> 8) * 256 + (size_t)jt * 128) * 256;
    const __half* X1P = g_X + (size_t)m * 65792;
    const __half* X2P = g_X + XSZ + (size_t)m * 65792;

    if (tid < 256) {
        h1s[tid] = h1[(size_t)m * 256 + tid];
        h2s[tid] = h2[(size_t)m * 256 + tid];
    }

    const int gq = lane >> 2, t = lane & 3;
    float acc[2][8][4];

    // ---------------- stage 1: A_r = l2 @ X2 + bias, *h2 -> P fp16 ----------
    ZERO_ACC(acc)
#define S1(buf, s) stage_f(sb + (buf) * FBUF, tid, AP, X2P, (s) * 32)
    FLOOP(S1, compute_f(acc, sb + (s % 3) * FBUF, warpM, warpN, lane))
#undef S1

#pragma unroll
    for (int mi = 0; mi < 2; ++mi) {
        int j0 = warpM * 32 + mi * 16 + gq;
#pragma unroll
        for (int ni = 0; ni < 8; ++ni) {
            int c = warpN * 64 + ni * 8 + t * 2;
            __half2 b2 = *reinterpret_cast<const __half2*>(X2P + 65536 + c);
            float b0 = __half2float(__low2half(b2));
            float b1 = __half2float(__high2half(b2));
            float v00 = (acc[mi][ni][0] + b0) * h2s[c];
            float v01 = (acc[mi][ni][1] + b1) * h2s[c + 1];
            float v10 = (acc[mi][ni][2] + b0) * h2s[c];
            float v11 = (acc[mi][ni][3] + b1) * h2s[c + 1];
            u32 chunk = (u32)(warpN * 8 + ni);
            u32 o0 = j0 * 512 + ((chunk ^ (j0 & 7)) << 4) + t * 4;
            int j1 = j0 + 8;
            u32 o1 = j1 * 512 + ((chunk ^ (j1 & 7)) << 4) + t * 4;
            *reinterpret_cast<__half2*>(smem + FSM_P + o0) =
                __floats2half2_rn(v00, v01);
            *reinterpret_cast<__half2*>(smem + FSM_P + o1) =
                __floats2half2_rn(v10, v11);
        }
    }
    __syncthreads();   // P complete before stage-2 staging/compute

    // ---------------- stage 2: T = P @ W3T (1-term), *h1 -> T ---------------
    ZERO_ACC(acc)
#define S2(buf, s) stage_fB(sb + (buf) * FBUF, tid, g_W3T, (s) * 32)
    FLOOP(S2, compute_fp1(acc, pHi, sb + (s % 3) * FBUF, s * 4, warpM, warpN, lane))
#undef S2

    __syncthreads();   // all P reads done; safe to overwrite with T
#pragma unroll
    for (int mi = 0; mi < 2; ++mi) {
        int j0 = warpM * 32 + mi * 16 + gq;
#pragma unroll
        for (int ni = 0; ni < 8; ++ni) {
            int c = warpN * 64 + ni * 8 + t * 2;
            float s0 = h1s[c], s1 = h1s[c + 1];
            *reinterpret_cast<float2*>(Tp + (size_t)j0 * 260 + c) =
                make_float2(acc[mi][ni][0] * s0, acc[mi][ni][1] * s1);
            *reinterpret_cast<float2*>(Tp + (size_t)(j0 + 8) * 260 + c) =
                make_float2(acc[mi][ni][2] * s0, acc[mi][ni][3] * s1);
        }
    }
    __syncthreads();   // T visible before stage-3 epilogue; bufs free

    // ---------------- stage 3: A_l = l2 @ X1 + bias; dot with T -------------
    ZERO_ACC(acc)
#define S3(buf, s) stage_f(sb + (buf) * FBUF, tid, AP, X1P, (s) * 32)
    FLOOP(S3, compute_f(acc, sb + (s % 3) * FBUF, warpM, warpN, lane))
#undef S3

    float rs[2][2] = {{0.0f, 0.0f}, {0.0f, 0.0f}};
#pragma unroll
    for (int mi = 0; mi < 2; ++mi) {
        int j0 = warpM * 32 + mi * 16 + gq;
#pragma unroll
        for (int ni = 0; ni < 8; ++ni) {
            int c = warpN * 64 + ni * 8 + t * 2;
            __half2 b2 = *reinterpret_cast<const __half2*>(X1P + 65536 + c);
            float b0 = __half2float(__low2half(b2));
            float b1 = __half2float(__high2half(b2));
            float2 t0 = *reinterpret_cast<const float2*>(Tp + (size_t)j0 * 260 + c);
            float2 t1 = *reinterpret_cast<const float2*>(Tp + (size_t)(j0 + 8) * 260 + c);
            rs[mi][0] += (acc[mi][ni][0] + b0) * t0.x + (acc[mi][ni][1] + b1) * t0.y;
            rs[mi][1] += (acc[mi][ni][2] + b0) * t1.x + (acc[mi][ni][3] + b1) * t1.y;
        }
    }

    // reduce over the 4 lanes (t) sharing each row, then across warpN
#pragma unroll
    for (int mi = 0; mi < 2; ++mi)
#pragma unroll
        for (int h = 0; h < 2; ++h) {
            rs[mi][h] += __shfl_xor_sync(0xffffffffu, rs[mi][h], 1);
            rs[mi][h] += __shfl_xor_sync(0xffffffffu, rs[mi][h], 2);
        }
    if (t == 0) {
#pragma unroll
        for (int mi = 0; mi < 2; ++mi) {
            red[warpN * 128 + warpM * 32 + mi * 16 + gq]     = rs[mi][0];
            red[warpN * 128 + warpM * 32 + mi * 16 + 8 + gq] = rs[mi][1];
        }
    }
    __syncthreads();
    if (tid < 128)
        out[(size_t)m * 256 + jt * 128 + tid] =
            red[tid] + red[128 + tid] + red[256 + tid] + red[384 + tid];
}

// ---------------------------------------------------------------------------
extern "C" void kernel_launch(void* const* d_in, const int* in_sizes, int n_in,
                              void* d_out, int out_size)
{
    const float* layer1 = (const float*)d_in[0];
    const float* layer2 = (const float*)d_in[1];
    const float* h1     = (const float*)d_in[2];
    const float* h2     = (const float*)d_in[3];
    const float* W1     = (const float*)d_in[4];
    const float* W2     = (const float*)d_in[5];
    const float* W3     = (const float*)d_in[6];
    float* out = (float*)d_out;

    cudaFuncSetAttribute(k1_gemm,   cudaFuncAttributeMaxDynamicSharedMemorySize, SMEM12);
    cudaFuncSetAttribute(k23_fused, cudaFuncAttributeMaxDynamicSharedMemorySize, FSMEM);

    k_prep<<<256,  256>>>(layer1, 0, 524288ull);
    k_prep<<<256,  256>>>(layer2, 1, 524288ull);
    k_prep<<<8257, 256>>>(W1, 2, WSZ);
    k_prep<<<8257, 256>>>(W2, 3, WSZ);
    k_prep_w3<<<dim3(8, 8), dim3(32, 32)>>>(W3);

    k1_gemm<<<dim3(16, 514, 2), 256, SMEM12>>>();
    k23_fused<<<dim3(2, 2048), 512, FSMEM>>>(h1, h2, out);
}